// round 12
// baseline (speedup 1.0000x reference)
#include <cuda_runtime.h>
#include <cstdint>
#include <math.h>

#define BB 32
#define DD 1024
#define HH 64
#define OO 1000
#define EE 6
#define NBLK 128
#define NTHR 256
#define CLUSTER 4
#define TX_BYTES (2 * HH * 4)   // 512: bytes arriving into each CTA's hs

__device__ __forceinline__ void fma4(float4& acc, float v, const float4& w) {
    acc.x += v * w.x; acc.y += v * w.y; acc.z += v * w.z; acc.w += v * w.w;
}

__device__ __forceinline__ unsigned int smem_u32(const void* p) {
    unsigned int a;
    asm("{ .reg .u64 t; cvta.to.shared.u64 t, %1; cvt.u32.u64 %0, t; }"
        : "=r"(a) : "l"(p));
    return a;
}

// Async store of one float into cluster CTA `rank`'s smem, completing on that
// CTA's mbarrier (tx-bytes accounting). Both addresses mapped via mapa.
__device__ __forceinline__ void dsmem_store_async(unsigned int local_addr,
                                                  unsigned int local_mbar,
                                                  int rank, float v) {
    unsigned int ra, rm;
    asm volatile("mapa.shared::cluster.u32 %0, %1, %2;"
                 : "=r"(ra) : "r"(local_addr), "r"(rank));
    asm volatile("mapa.shared::cluster.u32 %0, %1, %2;"
                 : "=r"(rm) : "r"(local_mbar), "r"(rank));
    asm volatile("st.async.weak.shared::cluster.mbarrier::complete_tx::bytes.f32"
                 " [%0], %1, [%2];"
                 :: "r"(ra), "f"(v), "r"(rm) : "memory");
}

__global__ void __launch_bounds__(NTHR) __cluster_dims__(CLUSTER, 1, 1)
moe_fused(const float* __restrict__ x,
          const float* __restrict__ gw,
          const float* __restrict__ gb,
          const float* __restrict__ w1,
          const float* __restrict__ b1,
          const float* __restrict__ w2,
          const float* __restrict__ b2,
          float* __restrict__ out) {
    const int bid = blockIdx.x;
    const int tid = threadIdx.x;
    const int warp = tid >> 5, lane = tid & 31;

    __shared__ __align__(16) float xs[DD];          // 4 KB
    __shared__ __align__(16) float part[8][32];     // 1 KB
    __shared__ __align__(16) float hs[2 * HH];      // row b's full h (both slots)
    __shared__ __align__(8)  unsigned long long mbar;
    __shared__ float logit[EE];

    // Cluster = the 4 blocks of row b. Phase-1 role (k, ch), phase-2 role oc.
    const int b = bid >> 2, k = (bid >> 1) & 1, ch = bid & 1;
    const int oc = bid & 3;

    const unsigned int mbar_a = smem_u32(&mbar);

    // ---- init mbarrier + expect_tx, then NON-BLOCKING cluster arrive -------
    if (tid == 0) {
        asm volatile("mbarrier.init.shared.b64 [%0], 1;" :: "r"(mbar_a) : "memory");
        asm volatile("mbarrier.arrive.expect_tx.shared.b64 _, [%0], %1;"
                     :: "r"(mbar_a), "r"((unsigned)TX_BYTES) : "memory");
    }
    __syncthreads();                                  // mbar init visible block-wide
    asm volatile("barrier.cluster.arrive.aligned;" ::: "memory");  // release: publishes init

    // ---- stage x to smem (1 float4/thread) + gate logits from GLOBAL x -----
    ((float4*)xs)[tid] = ((const float4*)(x + b * DD))[tid];
    if (warp < EE) {
        const float* xr = x + b * DD;
        float s0 = 0.f, s1 = 0.f, s2 = 0.f, s3 = 0.f;
        #pragma unroll
        for (int i = 0; i < DD / 128; ++i) {        // 4-way chain split
            int d = lane + 128 * i;
            s0 += xr[d]      * gw[(d)      * EE + warp];
            s1 += xr[d + 32] * gw[(d + 32) * EE + warp];
            s2 += xr[d + 64] * gw[(d + 64) * EE + warp];
            s3 += xr[d + 96] * gw[(d + 96) * EE + warp];
        }
        float s = (s0 + s1) + (s2 + s3);
        #pragma unroll
        for (int off = 16; off > 0; off >>= 1)
            s += __shfl_down_sync(0xFFFFFFFFu, s, off);
        if (lane == 0) logit[warp] = s + gb[warp];
    }
    __syncthreads();

    // ---- top-2 + 2-way softmax (every thread; kept in registers) ----------
    float v[EE];
    #pragma unroll
    for (int e = 0; e < EE; ++e) v[e] = logit[e];
    int i1 = 0; float m1 = v[0];
    #pragma unroll
    for (int e = 1; e < EE; ++e) if (v[e] > m1) { m1 = v[e]; i1 = e; }
    int i2 = -1; float m2 = -INFINITY;
    #pragma unroll
    for (int e = 0; e < EE; ++e) if (e != i1 && v[e] > m2) { m2 = v[e]; i2 = e; }
    const float g1  = 1.0f / (1.0f + __expf(m2 - m1));  // m1 >= m2: stable
    const float gk  = (k == 0) ? g1 : (1.0f - g1);
    const int   e   = (k == 0) ? i1 : i2;
    const int   e0  = i1, e1 = i2;
    const float gk0 = g1, gk1 = 1.0f - g1;

    // Prefetch fc1 bias early (consumed after the reduce)
    const float biasv = __ldg(&b1[e * HH + ch * 32 + (tid & 31)]);

    // ---- fc1 (32 cols of half ch): dg=tid>>3 (32 d-groups), cg=tid&7 -------
    float4 t;
    {
        const int dg = tid >> 3, cg = tid & 7;
        const float* wbase = w1 + ((size_t)e * DD + dg * 32) * HH + ch * 32 + cg * 4;
        const float* xp = xs + dg * 32;
        float4 a0 = {0,0,0,0}, a1 = {0,0,0,0}, a2 = {0,0,0,0}, a3 = {0,0,0,0};
        #pragma unroll
        for (int d = 0; d < 32; d += 4) {
            fma4(a0, xp[d + 0], *(const float4*)(wbase + (d + 0) * HH));
            fma4(a1, xp[d + 1], *(const float4*)(wbase + (d + 1) * HH));
            fma4(a2, xp[d + 2], *(const float4*)(wbase + (d + 2) * HH));
            fma4(a3, xp[d + 3], *(const float4*)(wbase + (d + 3) * HH));
        }
        t.x = (a0.x + a1.x) + (a2.x + a3.x);
        t.y = (a0.y + a1.y) + (a2.y + a3.y);
        t.z = (a0.z + a1.z) + (a2.z + a3.z);
        t.w = (a0.w + a1.w) + (a2.w + a3.w);
    }

    // ---- PRE-HANDOFF PREFETCH of all phase-2 w2/b2 data into registers -----
    const int g  = tid >> 2;                 // float4 group within O-chunk
    const int s  = tid & 3;                  // k-quarter (16 k each)
    const int olen = (oc < 3) ? 256 : 232;
    const int ng = olen >> 2;
    const int gg = (g < ng) ? g : (ng - 1);  // clamp for safe loads
    const int o  = oc * 256 + gg * 4;

    float4 w2r0[16], w2r1[16];
    const float* p0 = w2 + ((size_t)e0 * HH + s * 16) * OO + o;
    const float* p1 = w2 + ((size_t)e1 * HH + s * 16) * OO + o;
    #pragma unroll
    for (int j = 0; j < 16; ++j) w2r0[j] = __ldg((const float4*)(p0 + j * OO));
    #pragma unroll
    for (int j = 0; j < 16; ++j) w2r1[j] = __ldg((const float4*)(p1 + j * OO));
    const float4 bb0 = __ldg((const float4*)(b2 + (size_t)e0 * OO + o));
    const float4 bb1 = __ldg((const float4*)(b2 + (size_t)e1 * OO + o));

    // ---- finish fc1: fold 4 d-groups in-warp via shfl, then 8-deep smem ----
    #pragma unroll
    for (int off = 16; off >= 8; off >>= 1) {
        t.x += __shfl_xor_sync(0xFFFFFFFFu, t.x, off);
        t.y += __shfl_xor_sync(0xFFFFFFFFu, t.y, off);
        t.z += __shfl_xor_sync(0xFFFFFFFFu, t.z, off);
        t.w += __shfl_xor_sync(0xFFFFFFFFu, t.w, off);
    }
    if (lane < 8) *(float4*)&part[warp][lane * 4] = t;
    __syncthreads();

    // ---- producers: wait (pre-arrived) then async-push h to all 4 CTAs -----
    asm volatile("barrier.cluster.wait.aligned;" ::: "memory");  // acquire: mbars valid
    if (tid < 32) {
        float sum = biasv;
        #pragma unroll
        for (int w = 0; w < 8; ++w) sum += part[w][tid];
        const float hv = gk * fmaxf(sum, 0.0f);
        const unsigned int la = smem_u32(&hs[k * HH + ch * 32 + tid]);
        #pragma unroll
        for (int r = 0; r < CLUSTER; ++r) dsmem_store_async(la, mbar_a, r, hv);
    }

    // ---- consumers: wait only for OUR 512 bytes (tx-complete) --------------
    asm volatile(
        "{\n\t"
        ".reg .pred p;\n\t"
        "WAIT%=:\n\t"
        "mbarrier.try_wait.parity.acquire.cluster.shared::cta.b64 p, [%0], 0;\n\t"
        "@!p bra WAIT%=;\n\t"
        "}"
        :: "r"(mbar_a) : "memory");

    // ---- PHASE 2: h from LOCAL smem, w2/b2 from registers ------------------
    float4 acc = {0, 0, 0, 0};
    {
        const float4* h0p = (const float4*)(hs + s * 16);
        const float4* h1p = (const float4*)(hs + HH + s * 16);
        #pragma unroll
        for (int q = 0; q < 4; ++q) {
            float4 hq = h0p[q];
            fma4(acc, hq.x, w2r0[q * 4 + 0]);
            fma4(acc, hq.y, w2r0[q * 4 + 1]);
            fma4(acc, hq.z, w2r0[q * 4 + 2]);
            fma4(acc, hq.w, w2r0[q * 4 + 3]);
        }
        #pragma unroll
        for (int q = 0; q < 4; ++q) {
            float4 hq = h1p[q];
            fma4(acc, hq.x, w2r1[q * 4 + 0]);
            fma4(acc, hq.y, w2r1[q * 4 + 1]);
            fma4(acc, hq.z, w2r1[q * 4 + 2]);
            fma4(acc, hq.w, w2r1[q * 4 + 3]);
        }
    }

    // reduce across the 4 k-quarters (lanes 4g+s share a warp)
    #pragma unroll
    for (int off = 1; off <= 2; off <<= 1) {
        acc.x += __shfl_xor_sync(0xFFFFFFFFu, acc.x, off);
        acc.y += __shfl_xor_sync(0xFFFFFFFFu, acc.y, off);
        acc.z += __shfl_xor_sync(0xFFFFFFFFu, acc.z, off);
        acc.w += __shfl_xor_sync(0xFFFFFFFFu, acc.w, off);
    }

    if (g < ng && s == 0) {
        float4 r;
        r.x = acc.x + gk0 * bb0.x + gk1 * bb1.x;
        r.y = acc.y + gk0 * bb0.y + gk1 * bb1.y;
        r.z = acc.z + gk0 * bb0.z + gk1 * bb1.z;
        r.w = acc.w + gk0 * bb0.w + gk1 * bb1.w;
        *(float4*)(out + b * OO + o) = r;
    }

    // No trailing cluster sync needed: every CTA waits on its own mbarrier,
    // which only completes after ALL remote stores into it have landed, and
    // producers' st.async are fire-and-forget into still-resident CTAs.
    // Cluster CTAs are co-scheduled and none exits before its own mbarrier
    // completes, which transitively requires all producers' stores to have
    // been issued; in-flight st.async to an exiting CTA is the only hazard,
    // and each CTA's exit is gated on receiving all 512 bytes, so no store
    // can target an already-exited CTA.
}

// Inputs: x, gate_w, gate_b, w1, b1, w2, b2. Output: f32 [32,1000]
extern "C" void kernel_launch(void* const* d_in, const int* in_sizes, int n_in,
                              void* d_out, int out_size) {
    const float* x  = (const float*)d_in[0];
    const float* gw = (const float*)d_in[1];
    const float* gb = (const float*)d_in[2];
    const float* w1 = (const float*)d_in[3];
    const float* b1 = (const float*)d_in[4];
    const float* w2 = (const float*)d_in[5];
    const float* b2 = (const float*)d_in[6];
    float* out = (float*)d_out;

    moe_fused<<<NBLK, NTHR>>>(x, gw, gb, w1, b1, w2, b2, out);
}

// round 13
// speedup vs baseline: 1.0402x; 1.0402x over previous
#include <cuda_runtime.h>
#include <cstdint>
#include <math.h>

#define BB 32
#define DD 1024
#define HH 64
#define OO 1000
#define EE 6
#define NBLK 128
#define NTHR 256
#define CLUSTER 4
// Padded x layout: 32-float chunks padded by 4 floats -> chunk dg starts at
// float dg*36 (bank 4*dg) so a warp's 4 dg-groups never collide.
#define XSP (DD + DD / 8)

__device__ __forceinline__ void fma4(float4& acc, float v, const float4& w) {
    acc.x += v * w.x; acc.y += v * w.y; acc.z += v * w.z; acc.w += v * w.w;
}

__device__ __forceinline__ unsigned int smem_u32(const void* p) {
    unsigned int a;
    asm("{ .reg .u64 t; cvta.to.shared.u64 t, %1; cvt.u32.u64 %0, t; }"
        : "=r"(a) : "l"(p));
    return a;
}

// Store one float into the same smem offset of cluster CTA `rank`.
__device__ __forceinline__ void dsmem_store(unsigned int local_addr, int rank, float v) {
    unsigned int rem;
    asm volatile("mapa.shared::cluster.u32 %0, %1, %2;"
                 : "=r"(rem) : "r"(local_addr), "r"(rank));
    asm volatile("st.shared::cluster.f32 [%0], %1;"
                 :: "r"(rem), "f"(v) : "memory");
}

__global__ void __launch_bounds__(NTHR) __cluster_dims__(CLUSTER, 1, 1)
moe_fused(const float* __restrict__ x,
          const float* __restrict__ gw,
          const float* __restrict__ gb,
          const float* __restrict__ w1,
          const float* __restrict__ b1,
          const float* __restrict__ w2,
          const float* __restrict__ b2,
          float* __restrict__ out) {
    const int bid = blockIdx.x;
    const int tid = threadIdx.x;
    const int warp = tid >> 5, lane = tid & 31;

    __shared__ __align__(16) float xs[XSP];         // padded x row
    __shared__ __align__(16) float part[8][32];     // 1 KB
    __shared__ __align__(16) float hs[2 * HH];      // row b's full h (both slots)
    __shared__ float logit[EE];

    // Cluster = the 4 blocks of row b. Phase-1 role (k, ch), phase-2 role oc.
    const int b = bid >> 2, k = (bid >> 1) & 1, ch = bid & 1;
    const int oc = bid & 3;

    // ---- stage x to padded smem + gate logits from GLOBAL x ----------------
    ((float4*)xs)[tid + (tid >> 3)] = ((const float4*)(x + b * DD))[tid];
    if (warp < EE) {
        const float* xr = x + b * DD;
        float s0 = 0.f, s1 = 0.f, s2 = 0.f, s3 = 0.f;
        #pragma unroll
        for (int i = 0; i < DD / 128; ++i) {        // 4-way chain split
            int d = lane + 128 * i;
            s0 += xr[d]      * gw[(d)      * EE + warp];
            s1 += xr[d + 32] * gw[(d + 32) * EE + warp];
            s2 += xr[d + 64] * gw[(d + 64) * EE + warp];
            s3 += xr[d + 96] * gw[(d + 96) * EE + warp];
        }
        float s = (s0 + s1) + (s2 + s3);
        #pragma unroll
        for (int off = 16; off > 0; off >>= 1)
            s += __shfl_down_sync(0xFFFFFFFFu, s, off);
        if (lane == 0) logit[warp] = s + gb[warp];
    }
    __syncthreads();

    // ---- top-2 + 2-way softmax (every thread; kept in registers) ----------
    float v[EE];
    #pragma unroll
    for (int e = 0; e < EE; ++e) v[e] = logit[e];
    int i1 = 0; float m1 = v[0];
    #pragma unroll
    for (int e = 1; e < EE; ++e) if (v[e] > m1) { m1 = v[e]; i1 = e; }
    int i2 = -1; float m2 = -INFINITY;
    #pragma unroll
    for (int e = 0; e < EE; ++e) if (e != i1 && v[e] > m2) { m2 = v[e]; i2 = e; }
    const float g1  = 1.0f / (1.0f + __expf(m2 - m1));  // m1 >= m2: stable
    const float gk  = (k == 0) ? g1 : (1.0f - g1);
    const int   e   = (k == 0) ? i1 : i2;
    const int   e0  = i1, e1 = i2;
    const float gk0 = g1, gk1 = 1.0f - g1;

    // Prefetch fc1 bias early (consumed after the reduce)
    const float biasv = __ldg(&b1[e * HH + ch * 32 + (tid & 31)]);

    // ---- fc1 (32 cols of half ch): dg=tid>>3 (32 d-groups), cg=tid&7 -------
    float4 t;
    {
        const int dg = tid >> 3, cg = tid & 7;
        const float* wbase = w1 + ((size_t)e * DD + dg * 32) * HH + ch * 32 + cg * 4;
        const float* xp = xs + dg * 36;             // padded chunk, bank 4*dg
        float4 a0 = {0,0,0,0}, a1 = {0,0,0,0}, a2 = {0,0,0,0}, a3 = {0,0,0,0};
        #pragma unroll
        for (int d = 0; d < 32; d += 4) {
            fma4(a0, xp[d + 0], *(const float4*)(wbase + (d + 0) * HH));
            fma4(a1, xp[d + 1], *(const float4*)(wbase + (d + 1) * HH));
            fma4(a2, xp[d + 2], *(const float4*)(wbase + (d + 2) * HH));
            fma4(a3, xp[d + 3], *(const float4*)(wbase + (d + 3) * HH));
        }
        t.x = (a0.x + a1.x) + (a2.x + a3.x);
        t.y = (a0.y + a1.y) + (a2.y + a3.y);
        t.z = (a0.z + a1.z) + (a2.z + a3.z);
        t.w = (a0.w + a1.w) + (a2.w + a3.w);
    }

    // ---- PRE-BARRIER PREFETCH of all phase-2 w2/b2 data into registers -----
    const int g  = tid >> 2;                 // float4 group within O-chunk
    const int s  = tid & 3;                  // k-quarter (16 k each)
    const int olen = (oc < 3) ? 256 : 232;
    const int ng = olen >> 2;
    const int gg = (g < ng) ? g : (ng - 1);  // clamp for safe loads
    const int o  = oc * 256 + gg * 4;

    float4 w2r0[16], w2r1[16];
    const float* p0 = w2 + ((size_t)e0 * HH + s * 16) * OO + o;
    const float* p1 = w2 + ((size_t)e1 * HH + s * 16) * OO + o;
    #pragma unroll
    for (int j = 0; j < 16; ++j) w2r0[j] = __ldg((const float4*)(p0 + j * OO));
    #pragma unroll
    for (int j = 0; j < 16; ++j) w2r1[j] = __ldg((const float4*)(p1 + j * OO));
    const float4 bb0 = __ldg((const float4*)(b2 + (size_t)e0 * OO + o));
    const float4 bb1 = __ldg((const float4*)(b2 + (size_t)e1 * OO + o));

    // ---- finish fc1: fold 4 d-groups in-warp via shfl, then 8-deep smem ----
    #pragma unroll
    for (int off = 16; off >= 8; off >>= 1) {
        t.x += __shfl_xor_sync(0xFFFFFFFFu, t.x, off);
        t.y += __shfl_xor_sync(0xFFFFFFFFu, t.y, off);
        t.z += __shfl_xor_sync(0xFFFFFFFFu, t.z, off);
        t.w += __shfl_xor_sync(0xFFFFFFFFu, t.w, off);
    }
    if (lane < 8) *(float4*)&part[warp][lane * 4] = t;
    __syncthreads();

    // ---- broadcast this block's 32 h values into all 4 cluster CTAs' smem --
    if (tid < 32) {
        float sum = biasv;
        #pragma unroll
        for (int w = 0; w < 8; ++w) sum += part[w][tid];
        const float hv = gk * fmaxf(sum, 0.0f);
        const unsigned int la = smem_u32(&hs[k * HH + ch * 32 + tid]);
        #pragma unroll
        for (int r = 0; r < CLUSTER; ++r) dsmem_store(la, r, hv);
    }

    // ---- CLUSTER BARRIER: h now complete in every CTA's local smem ---------
    asm volatile("barrier.cluster.arrive.aligned;" ::: "memory");
    asm volatile("barrier.cluster.wait.aligned;"   ::: "memory");

    // ---- PHASE 2: h from LOCAL smem, w2/b2 from registers ------------------
    float4 acc = {0, 0, 0, 0};
    {
        const float4* h0p = (const float4*)(hs + s * 16);
        const float4* h1p = (const float4*)(hs + HH + s * 16);
        #pragma unroll
        for (int q = 0; q < 4; ++q) {
            float4 hq = h0p[q];
            fma4(acc, hq.x, w2r0[q * 4 + 0]);
            fma4(acc, hq.y, w2r0[q * 4 + 1]);
            fma4(acc, hq.z, w2r0[q * 4 + 2]);
            fma4(acc, hq.w, w2r0[q * 4 + 3]);
        }
        #pragma unroll
        for (int q = 0; q < 4; ++q) {
            float4 hq = h1p[q];
            fma4(acc, hq.x, w2r1[q * 4 + 0]);
            fma4(acc, hq.y, w2r1[q * 4 + 1]);
            fma4(acc, hq.z, w2r1[q * 4 + 2]);
            fma4(acc, hq.w, w2r1[q * 4 + 3]);
        }
    }

    // reduce across the 4 k-quarters (lanes 4g+s share a warp)
    #pragma unroll
    for (int off = 1; off <= 2; off <<= 1) {
        acc.x += __shfl_xor_sync(0xFFFFFFFFu, acc.x, off);
        acc.y += __shfl_xor_sync(0xFFFFFFFFu, acc.y, off);
        acc.z += __shfl_xor_sync(0xFFFFFFFFu, acc.z, off);
        acc.w += __shfl_xor_sync(0xFFFFFFFFu, acc.w, off);
    }

    if (g < ng && s == 0) {
        float4 r;
        r.x = acc.x + gk0 * bb0.x + gk1 * bb1.x;
        r.y = acc.y + gk0 * bb0.y + gk1 * bb1.y;
        r.z = acc.z + gk0 * bb0.z + gk1 * bb1.z;
        r.w = acc.w + gk0 * bb0.w + gk1 * bb1.w;
        *(float4*)(out + b * OO + o) = r;
    }
}

// Inputs: x, gate_w, gate_b, w1, b1, w2, b2. Output: f32 [32,1000]
extern "C" void kernel_launch(void* const* d_in, const int* in_sizes, int n_in,
                              void* d_out, int out_size) {
    const float* x  = (const float*)d_in[0];
    const float* gw = (const float*)d_in[1];
    const float* gb = (const float*)d_in[2];
    const float* w1 = (const float*)d_in[3];
    const float* b1 = (const float*)d_in[4];
    const float* w2 = (const float*)d_in[5];
    const float* b2 = (const float*)d_in[6];
    float* out = (float*)d_out;

    moe_fused<<<NBLK, NTHR>>>(x, gw, gb, w1, b1, w2, b2, out);
}